// round 4
// baseline (speedup 1.0000x reference)
#include <cuda_runtime.h>
#include <cstdint>

#define BATCH   2
#define HIMG    256
#define WIMG    256
#define CH      96
#define C3      288
#define WINSZ   16
#define SEQ     256
#define NHEADS  4
#define HD      24
#define NWIN    512
#define NTOK    131072

typedef unsigned long long ull;

__device__ float g_qkv[(size_t)NTOK * C3];
__device__ float g_o  [(size_t)NTOK * CH];

__device__ __forceinline__ ull pk2(float lo, float hi) {
    ull r; asm("mov.b64 %0, {%1,%2};" : "=l"(r) : "f"(lo), "f"(hi)); return r;
}
__device__ __forceinline__ void upk2(ull v, float& lo, float& hi) {
    asm("mov.b64 {%0,%1}, %2;" : "=f"(lo), "=f"(hi) : "l"(v));
}
__device__ __forceinline__ ull ffma2(ull a, ull b, ull c) {
    ull d; asm("fma.rn.f32x2 %0, %1, %2, %3;" : "=l"(d) : "l"(a), "l"(b), "l"(c));
    return d;
}

// ---------------------------------------------------------------------------
// GEMM: out[m, n0+n] = sum_k A[m,k]*W[k, n0+n] + bias[n0+n]
// M tile 128, N tile 96 (n0 = 96*blockIdx.y). 256 threads, 8x6 micro-tile,
// f32x2 row-pair packing. Explicit 2-stage software pipeline on the k-loop:
// k+1 operands prefetched into registers while k computes (hides 29cy LDS).
// ---------------------------------------------------------------------------
#define AS_LD 128
#define BS_LD 96

__global__ __launch_bounds__(256, 2)
void gemm_tok96(const float* __restrict__ A, const float* __restrict__ W,
                const float* __restrict__ bias, float* __restrict__ out,
                int wld, int oldd)
{
    extern __shared__ float sm[];
    float* As = sm;                 // [96][128]  As[k*128 + m]
    float* Bs = sm + 96 * AS_LD;    // [96][96]   Bs[k*96 + n]

    const int tid = threadIdx.x;
    const int m0  = blockIdx.x * 128;
    const int n0  = blockIdx.y * 96;

    // A tile, transposed into smem (2 threads per token row)
    {
        int m    = tid >> 1;
        int half = tid & 1;
        const float4* src = (const float4*)(A + (size_t)(m0 + m) * CH + half * 48);
        #pragma unroll
        for (int i = 0; i < 12; i++) {
            float4 v = src[i];
            int k = half * 48 + i * 4;
            As[(k + 0) * AS_LD + m] = v.x;
            As[(k + 1) * AS_LD + m] = v.y;
            As[(k + 2) * AS_LD + m] = v.z;
            As[(k + 3) * AS_LD + m] = v.w;
        }
    }
    // B tile
    for (int idx = tid; idx < 96 * 24; idx += 256) {
        int k  = idx / 24;
        int c4 = idx - k * 24;
        float4 v = *(const float4*)(W + (size_t)k * wld + n0 + c4 * 4);
        float* dst = Bs + k * BS_LD + c4 * 4;
        dst[0] = v.x; dst[1] = v.y; dst[2] = v.z; dst[3] = v.w;
    }
    __syncthreads();

    const int ty = tid >> 4;   // rows ty*8 .. ty*8+7
    const int tx = tid & 15;   // cols tx*6 .. tx*6+5

    ull acc[4][6];
    #pragma unroll
    for (int i = 0; i < 4; i++)
        #pragma unroll
        for (int j = 0; j < 6; j++) acc[i][j] = 0ULL;

    const float* a_base = As + ty * 8;
    const float* b_base = Bs + tx * 6;

    // ---- software-pipelined k-loop: prefetch k+1 while computing k ----
    ulonglong2 a01 = ((const ulonglong2*)a_base)[0];
    ulonglong2 a23 = ((const ulonglong2*)a_base)[1];
    float2 b01 = ((const float2*)b_base)[0];
    float2 b23 = ((const float2*)b_base)[1];
    float2 b45 = ((const float2*)b_base)[2];

    #pragma unroll 8
    for (int k = 0; k < 96; k++) {
        ull a2[4] = { a01.x, a01.y, a23.x, a23.y };
        float bv[6] = { b01.x, b01.y, b23.x, b23.y, b45.x, b45.y };

        if (k < 95) {
            const ulonglong2* an = (const ulonglong2*)(a_base + (k + 1) * AS_LD);
            const float2*     bn = (const float2*)(b_base + (k + 1) * BS_LD);
            a01 = an[0]; a23 = an[1];
            b01 = bn[0]; b23 = bn[1]; b45 = bn[2];
        }

        #pragma unroll
        for (int j = 0; j < 6; j++) {
            ull b2 = pk2(bv[j], bv[j]);
            #pragma unroll
            for (int i = 0; i < 4; i++) acc[i][j] = ffma2(a2[i], b2, acc[i][j]);
        }
    }

    // epilogue: bias + STG.64
    float bvv[6];
    #pragma unroll
    for (int j = 0; j < 6; j++) bvv[j] = __ldg(bias + n0 + tx * 6 + j);

    #pragma unroll
    for (int i = 0; i < 4; i++) {
        size_t r0 = (size_t)(m0 + ty * 8 + 2 * i);
        float lo[6], hi[6];
        #pragma unroll
        for (int j = 0; j < 6; j++) {
            float l, h; upk2(acc[i][j], l, h);
            lo[j] = l + bvv[j]; hi[j] = h + bvv[j];
        }
        ull* d0 = (ull*)(out + r0 * oldd + n0 + tx * 6);
        ull* d1 = (ull*)(out + (r0 + 1) * oldd + n0 + tx * 6);
        d0[0] = pk2(lo[0], lo[1]); d0[1] = pk2(lo[2], lo[3]); d0[2] = pk2(lo[4], lo[5]);
        d1[0] = pk2(hi[0], hi[1]); d1[1] = pk2(hi[2], hi[3]); d1[2] = pk2(hi[4], hi[5]);
    }
}

// ---------------------------------------------------------------------------
// Fused attention + lepe per (window, head). 128 threads, 2 query rows each.
// K row for j+1 prefetched into registers while j's PV accumulates; V load
// latency hides under the QK FFMA2 tree.
// ---------------------------------------------------------------------------
__global__ __launch_bounds__(128, 3)
void attn_lepe(const float* __restrict__ qkv, const float* __restrict__ pe_w,
               const float* __restrict__ pe_b, float* __restrict__ og)
{
    extern __shared__ float sm[];
    float* ks = sm;            // [256][24]
    float* vs = sm + SEQ * HD; // [256][24]

    const int tid = threadIdx.x;
    const int n   = blockIdx.x;
    const int h   = blockIdx.y;
    const int b   = n >> 8;
    const int wr  = (n >> 4) & 15;
    const int wc  = n & 15;
    const int rowbase = wr * 16;
    const int colbase = wc * 16;

    auto tok = [&](int s) -> int {
        int r = s >> 4, c = s & 15;
        return b * 65536 + (rowbase + r) * 256 + (colbase + c);
    };

    // stage Q through smem (coalesced), pull own rows to regs
    for (int i = tid; i < SEQ * 6; i += 128) {
        int s = i / 6, qd = i - s * 6;
        ((float4*)ks)[i] = *(const float4*)(qkv + (size_t)tok(s) * C3 + h * 72 + qd * 4);
    }
    __syncthreads();
    ull q2[2][12];
    {
        const ull* qa = (const ull*)(ks + tid * HD);
        const ull* qb = (const ull*)(ks + (tid + 128) * HD);
        #pragma unroll
        for (int i = 0; i < 12; i++) { q2[0][i] = qa[i]; q2[1][i] = qb[i]; }
    }
    __syncthreads();

    // cooperative coalesced K/V loads
    for (int i = tid; i < SEQ * 6; i += 128) {
        int s = i / 6, qd = i - s * 6;
        size_t base = (size_t)tok(s) * C3 + h * 72;
        ((float4*)ks)[i] = *(const float4*)(qkv + base + 24 + qd * 4);
        ((float4*)vs)[i] = *(const float4*)(qkv + base + 48 + qd * 4);
    }
    __syncthreads();

    const float scale = 0.20412414523193154f; // 1/sqrt(24)

    ull acc[2][12];
    #pragma unroll
    for (int i = 0; i < 12; i++) { acc[0][i] = 0ULL; acc[1][i] = 0ULL; }
    float l0 = 0.f, l1 = 0.f;

    const ulonglong2* krow = (const ulonglong2*)ks;  // 6 ulonglong2 per row
    const ulonglong2* vrow4 = (const ulonglong2*)vs;

    // prefetch K row j=0
    ulonglong2 kf[3];
    ull kg[6];
    kf[0] = krow[0]; kf[1] = krow[1]; kf[2] = krow[2];
    kg[0] = krow[3].x; kg[1] = krow[3].y;
    kg[2] = krow[4].x; kg[3] = krow[4].y;
    kg[4] = krow[5].x; kg[5] = krow[5].y;

    #pragma unroll 2
    for (int j = 0; j < SEQ; j++) {
        // current K row from prefetch regs
        ull kcur[12];
        kcur[0] = kf[0].x; kcur[1] = kf[0].y;
        kcur[2] = kf[1].x; kcur[3] = kf[1].y;
        kcur[4] = kf[2].x; kcur[5] = kf[2].y;
        kcur[6] = kg[0]; kcur[7] = kg[1]; kcur[8] = kg[2];
        kcur[9] = kg[3]; kcur[10] = kg[4]; kcur[11] = kg[5];

        // prefetch next K row
        if (j < SEQ - 1) {
            const ulonglong2* kn = krow + (j + 1) * 6;
            kf[0] = kn[0]; kf[1] = kn[1]; kf[2] = kn[2];
            kg[0] = kn[3].x; kg[1] = kn[3].y;
            kg[2] = kn[4].x; kg[3] = kn[4].y;
            kg[4] = kn[5].x; kg[5] = kn[5].y;
        }

        ull d0 = 0ULL, d1 = 0ULL;
        #pragma unroll
        for (int i = 0; i < 12; i++) {
            d0 = ffma2(q2[0][i], kcur[i], d0);
            d1 = ffma2(q2[1][i], kcur[i], d1);
        }
        float a, bb;
        upk2(d0, a, bb); float s0 = (a + bb) * scale;
        upk2(d1, a, bb); float s1 = (a + bb) * scale;
        float p0 = __expf(s0), p1 = __expf(s1);
        l0 += p0; l1 += p1;
        ull p02 = pk2(p0, p0), p12 = pk2(p1, p1);
        const ulonglong2* v4 = vrow4 + j * 6;
        #pragma unroll
        for (int i = 0; i < 6; i++) {
            ulonglong2 vv = v4[i];
            acc[0][2 * i]     = ffma2(p02, vv.x, acc[0][2 * i]);
            acc[1][2 * i]     = ffma2(p12, vv.x, acc[1][2 * i]);
            acc[0][2 * i + 1] = ffma2(p02, vv.y, acc[0][2 * i + 1]);
            acc[1][2 * i + 1] = ffma2(p12, vv.y, acc[1][2 * i + 1]);
        }
    }

    // normalize, add lepe (3x3 depthwise on V image), store
    #pragma unroll
    for (int rr = 0; rr < 2; rr++) {
        int s = tid + rr * 128;
        float inv = 1.0f / (rr ? l1 : l0);
        float o[24];
        #pragma unroll
        for (int i = 0; i < 12; i++) {
            float lo, hi; upk2(acc[rr][i], lo, hi);
            o[2 * i]     = lo * inv;
            o[2 * i + 1] = hi * inv;
        }
        int r = s >> 4, c = s & 15;
        #pragma unroll
        for (int ky = -1; ky <= 1; ky++) {
            int r2 = r + ky;
            if (r2 < 0 || r2 > 15) continue;
            #pragma unroll
            for (int kx = -1; kx <= 1; kx++) {
                int c2 = c + kx;
                if (c2 < 0 || c2 > 15) continue;
                const float* vr = vs + (r2 * 16 + c2) * HD;
                const float* wrow = pe_w + ((ky + 1) * 3 + (kx + 1)) * CH + h * HD;
                #pragma unroll
                for (int d = 0; d < 24; d++) o[d] += vr[d] * __ldg(wrow + d);
            }
        }
        #pragma unroll
        for (int d = 0; d < 24; d++) o[d] += __ldg(pe_b + h * HD + d);

        float4* dst = (float4*)(og + (size_t)tok(s) * CH + h * HD);
        #pragma unroll
        for (int i = 0; i < 6; i++)
            dst[i] = make_float4(o[4 * i], o[4 * i + 1], o[4 * i + 2], o[4 * i + 3]);
    }
}

// ---------------------------------------------------------------------------
extern "C" void kernel_launch(void* const* d_in, const int* in_sizes, int n_in,
                              void* d_out, int out_size)
{
    const float* x     = (const float*)d_in[0];
    const float* qkv_w = (const float*)d_in[1];
    const float* qkv_b = (const float*)d_in[2];
    const float* pe_w  = (const float*)d_in[3];
    const float* pe_b  = (const float*)d_in[4];
    const float* out_w = (const float*)d_in[5];
    const float* out_b = (const float*)d_in[6];
    float* out = (float*)d_out;

    float* qkv_ptr = nullptr;
    float* o_ptr   = nullptr;
    cudaGetSymbolAddress((void**)&qkv_ptr, g_qkv);
    cudaGetSymbolAddress((void**)&o_ptr,   g_o);

    const int gemm_smem = (96 * AS_LD + 96 * BS_LD) * (int)sizeof(float); // 86016
    const int attn_smem = 2 * SEQ * HD * (int)sizeof(float);              // 49152
    cudaFuncSetAttribute(gemm_tok96, cudaFuncAttributeMaxDynamicSharedMemorySize, gemm_smem);
    cudaFuncSetAttribute(attn_lepe,  cudaFuncAttributeMaxDynamicSharedMemorySize, attn_smem);

    // 1) QKV projection: 3 N-tiles via blockIdx.y
    gemm_tok96<<<dim3(NTOK / 128, 3), 256, gemm_smem>>>(x, qkv_w, qkv_b, qkv_ptr, C3, C3);

    // 2) Fused windowed attention + lepe
    attn_lepe<<<dim3(NWIN, NHEADS), 128, attn_smem>>>(qkv_ptr, pe_w, pe_b, o_ptr);

    // 3) Output projection
    gemm_tok96<<<dim3(NTOK / 128, 1), 256, gemm_smem>>>(o_ptr, out_w, out_b, out, CH, CH);
}